// round 5
// baseline (speedup 1.0000x reference)
#include <cuda_runtime.h>

#define NPTS 16384
#define KNB  16

// Scratch (no allocations allowed).
__device__ __align__(16) float g_A[NPTS * 128];
__device__ int g_nbr[NPTS * KNB];
__device__ __align__(16) float4 g_pos4[NPTS];

// ---------------------------------------------------------------------------
// Pack pos -> float4 (x,y,z,|p|^2) once; both sides of d2 use the same sq.
// ---------------------------------------------------------------------------
__global__ void pos4_kernel(const float* __restrict__ pos) {
    const int i = blockIdx.x * blockDim.x + threadIdx.x;
    const float x = pos[3 * i], y = pos[3 * i + 1], z = pos[3 * i + 2];
    g_pos4[i] = make_float4(x, y, z, x * x + y * y + z * z);
}

// ---------------------------------------------------------------------------
// Warp-cooperative bitonic helpers on packed u64 keys (asc = smaller d2 first,
// ties broken by lower index via low 32 bits).
// ---------------------------------------------------------------------------
__device__ __forceinline__ unsigned long long sort32(unsigned long long v, int lane) {
#pragma unroll
    for (int k = 2; k <= 32; k <<= 1) {
#pragma unroll
        for (int j = k >> 1; j > 0; j >>= 1) {
            const unsigned long long o = __shfl_xor_sync(0xffffffffu, v, j);
            const bool keepMin = (((lane & j) == 0) == ((lane & k) == 0));
            v = ((v < o) == keepMin) ? v : o;
        }
    }
    return v;
}

// a, b sorted ascending across lanes; returns the lowest 32 of the 64, sorted.
__device__ __forceinline__ unsigned long long merge_lower(unsigned long long a,
                                                          unsigned long long b,
                                                          int lane) {
    const unsigned long long br = __shfl_sync(0xffffffffu, b, 31 - lane);
    unsigned long long m = (a < br) ? a : br;   // bitonic sequence
#pragma unroll
    for (int j = 16; j > 0; j >>= 1) {
        const unsigned long long o = __shfl_xor_sync(0xffffffffu, m, j);
        const bool keepMin = ((lane & j) == 0);
        m = ((m < o) == keepMin) ? m : o;
    }
    return m;
}

__device__ __forceinline__ void flush_merge(unsigned long long& v, float& kthf,
                                            const unsigned long long* buf,
                                            int cnt, int lane) {
    __syncwarp();
    unsigned long long b0 = (lane < cnt) ? buf[lane] : ~0ull;
    b0 = sort32(b0, lane);
    if (cnt > 32) {
        unsigned long long b1 = (32 + lane < cnt) ? buf[32 + lane] : ~0ull;
        b1 = sort32(b1, lane);
        b0 = merge_lower(b0, b1, lane);
    }
    v = merge_lower(v, b0, lane);
    const unsigned m = (unsigned)(__shfl_sync(0xffffffffu, v, 15) >> 32);
    // inverse monotone map: top bit set -> positive float, else negative.
    kthf = (m & 0x80000000u) ? __uint_as_float(m & 0x7fffffffu)
                             : __uint_as_float(~m);
}

// ---------------------------------------------------------------------------
// KNN: one warp handles RPW=4 rows; 32 candidates/iter shared across rows
// (1 LDS serves 4 rows). Float-threshold filter in the hot path; packed-key
// bitonic flush (exact ordering + index tie-break) only on hits.
// ---------------------------------------------------------------------------
#define WPB  8
#define RPW  4
#define TILE 1024
#define SENTINEL 0xFF7FFFFFFFFFFFFFull   // maps back to +FLT_MAX

__global__ void __launch_bounds__(32 * WPB) knn_kernel() {
    __shared__ float4 s_cand[TILE];
    __shared__ unsigned long long s_buf[WPB][RPW][64];

    const int lane = threadIdx.x & 31;
    const int w    = threadIdx.x >> 5;
    const int row0 = (blockIdx.x * WPB + w) * RPW;

    float4 p[RPW];
    unsigned long long v[RPW];
    float kthf[RPW];
    int cnt[RPW];
#pragma unroll
    for (int r = 0; r < RPW; ++r) {
        p[r] = g_pos4[row0 + r];
        v[r] = SENTINEL;
        kthf[r] = 3.402823466e38f;
        cnt[r] = 0;
    }

    for (int base = 0; base < NPTS; base += TILE) {
        __syncthreads();
        for (int i = threadIdx.x; i < TILE; i += 32 * WPB) s_cand[i] = g_pos4[base + i];
        __syncthreads();
#pragma unroll 2
        for (int i = 0; i < TILE; i += 32) {
            const float4 c = s_cand[i + lane];
#pragma unroll
            for (int r = 0; r < RPW; ++r) {
                const float dot = fmaf(p[r].x, c.x, fmaf(p[r].y, c.y, p[r].z * c.z));
                const float d2  = fmaf(-2.f, dot, p[r].w + c.w);
                const bool pred = d2 < kthf[r];
                const unsigned bal = __ballot_sync(0xffffffffu, pred);
                if (bal) {
                    if (pred) {
                        unsigned u = __float_as_uint(d2);
                        u = (u & 0x80000000u) ? ~u : (u | 0x80000000u);
                        s_buf[w][r][cnt[r] + __popc(bal & ((1u << lane) - 1u))] =
                            ((unsigned long long)u << 32) | (unsigned)(base + i + lane);
                    }
                    cnt[r] += __popc(bal);
                    if (cnt[r] > 32) {
                        flush_merge(v[r], kthf[r], s_buf[w][r], cnt[r], lane);
                        cnt[r] = 0;
                    }
                }
            }
        }
    }
#pragma unroll
    for (int r = 0; r < RPW; ++r) {
        if (cnt[r]) flush_merge(v[r], kthf[r], s_buf[w][r], cnt[r], lane);
        if (lane < KNB)
            g_nbr[(row0 + r) * KNB + lane] = (int)(v[r] & 0xFFFFFFFFull);
    }
}

// ---------------------------------------------------------------------------
// Node projection (unchanged from R4-passing version).
// ---------------------------------------------------------------------------
template <int CIN, int C, bool FIRST>
__global__ void __launch_bounds__(128) proj_kernel(const float* __restrict__ x,
                                                   const float* __restrict__ pos,
                                                   const float* __restrict__ nrm,
                                                   const float* __restrict__ Wa,
                                                   const float* __restrict__ ba) {
    constexpr int TPN = C / 4;
    __shared__ __align__(16) float sW[CIN * C];
    __shared__ __align__(16) float sb[C];
    const int t = threadIdx.x;
    for (int i = t; i < CIN * C; i += 128) sW[i] = Wa[i];
    for (int i = t; i < C; i += 128) sb[i] = ba[i];
    __syncthreads();

    const int n  = blockIdx.x * (128 / TPN) + t / TPN;
    const int c0 = (t % TPN) * 4;
    float4 acc = *reinterpret_cast<const float4*>(&sb[c0]);
#pragma unroll
    for (int k = 0; k < CIN; ++k) {
        float xv;
        if (FIRST) xv = (k < 3) ? pos[n * 3 + k] : nrm[n * 3 + (k - 3)];
        else       xv = x[n * CIN + k];
        const float4 w = *reinterpret_cast<const float4*>(&sW[k * C + c0]);
        acc.x = fmaf(xv, w.x, acc.x);
        acc.y = fmaf(xv, w.y, acc.y);
        acc.z = fmaf(xv, w.z, acc.z);
        acc.w = fmaf(xv, w.w, acc.w);
    }
    *reinterpret_cast<float4*>(&g_A[n * C + c0]) = acc;
}

// ---------------------------------------------------------------------------
// Fused edge kernel (unchanged from R4-passing version).
// ---------------------------------------------------------------------------
template <int C, int G, int NPB>
__global__ void __launch_bounds__(2 * C) edge_kernel(
    const float* __restrict__ pos,
    const float* __restrict__ Wa, int cin_node,
    const float* __restrict__ gmm, const float* __restrict__ bta,
    const float* __restrict__ Wb,  const float* __restrict__ bb,
    float* __restrict__ out) {
    constexpr int B  = 2 * C;
    constexpr int HS = 20;
    constexpr int NG = 4;
    extern __shared__ float smem[];
    float* s_Wb   = smem;
    float* s_H    = s_Wb + C * C;
    float* s_Wrel = s_H + NG * C * HS;
    float* s_g    = s_Wrel + 3 * C;
    float* s_b    = s_g + C;
    float* s_bb   = s_b + C;

    const int t = threadIdx.x;
    for (int i = t; i < C * C; i += B) s_Wb[i] = Wb[i];
    for (int i = t; i < 3 * C; i += B) s_Wrel[i] = Wa[cin_node * C + i];
    for (int i = t; i < C; i += B) { s_g[i] = gmm[i]; s_b[i] = bta[i]; s_bb[i] = bb[i]; }
    __syncthreads();

    const int e    = t & 15;
    const int g    = t >> 4;
    const int lane = t & 31;
    const int w    = t >> 5;
    const int et   = lane & 3;
    const int fi   = lane >> 2;
    const int q3   = (C == 128) ? (w >> 1) : w;
    const int f0   = ((C == 128) ? (w & 1) * 64 : 0) + fi * 8;

    for (int s0 = 0; s0 < NPB; s0 += NG) {
#pragma unroll
        for (int q = 0; q < NG; ++q) {
            const int i = blockIdx.x * NPB + s0 + q;
            float* Hq = s_H + q * C * HS;
            const int j = g_nbr[i * KNB + e];
            const float rx = pos[j * 3 + 0] - pos[i * 3 + 0];
            const float ry = pos[j * 3 + 1] - pos[i * 3 + 1];
            const float rz = pos[j * 3 + 2] - pos[i * 3 + 2];
            const int c0 = g * 8;
            const float* Ar = g_A + j * C + c0;
            const float4 a0 = *reinterpret_cast<const float4*>(Ar);
            const float4 a1 = *reinterpret_cast<const float4*>(Ar + 4);
            float h[8] = {a0.x, a0.y, a0.z, a0.w, a1.x, a1.y, a1.z, a1.w};
            float sum = 0.f;
#pragma unroll
            for (int cc = 0; cc < 8; ++cc) {
                const int c = c0 + cc;
                h[cc] = h[cc] + rx * s_Wrel[c] + ry * s_Wrel[C + c] + rz * s_Wrel[2 * C + c];
                sum += h[cc];
            }
            const float mean = sum * 0.125f;
            float vs = 0.f;
#pragma unroll
            for (int cc = 0; cc < 8; ++cc) { const float d = h[cc] - mean; vs = fmaf(d, d, vs); }
            const float inv = rsqrtf(fmaf(vs, 0.125f, 1e-5f));
#pragma unroll
            for (int cc = 0; cc < 8; ++cc) {
                const int c = c0 + cc;
                const float vv = fmaf((h[cc] - mean) * inv, s_g[c], s_b[c]);
                Hq[c * HS + e] = fmaxf(vv, 0.f);
            }
        }
        __syncthreads();
        {
            const int i = blockIdx.x * NPB + s0 + q3;
            const float* Hq = s_H + q3 * C * HS;
            float acc[4][8];
#pragma unroll
            for (int a = 0; a < 4; ++a)
#pragma unroll
                for (int f = 0; f < 8; ++f) acc[a][f] = 0.f;

#pragma unroll 4
            for (int c = 0; c < C; ++c) {
                const float4 h4 = *reinterpret_cast<const float4*>(&Hq[c * HS + et * 4]);
                const float4 wa = *reinterpret_cast<const float4*>(&s_Wb[c * C + f0]);
                const float4 wc = *reinterpret_cast<const float4*>(&s_Wb[c * C + f0 + 4]);
                const float he[4] = {h4.x, h4.y, h4.z, h4.w};
                const float wf[8] = {wa.x, wa.y, wa.z, wa.w, wc.x, wc.y, wc.z, wc.w};
#pragma unroll
                for (int a = 0; a < 4; ++a)
#pragma unroll
                    for (int f = 0; f < 8; ++f)
                        acc[a][f] = fmaf(he[a], wf[f], acc[a][f]);
            }
            float m[8];
#pragma unroll
            for (int f = 0; f < 8; ++f) {
                m[f] = fmaxf(fmaxf(acc[0][f], acc[1][f]), fmaxf(acc[2][f], acc[3][f]));
                m[f] = fmaxf(m[f], __shfl_xor_sync(0xffffffffu, m[f], 1));
                m[f] = fmaxf(m[f], __shfl_xor_sync(0xffffffffu, m[f], 2));
            }
            if (et == 0) {
                float4 r0, r1;
                r0.x = fmaxf(m[0] + s_bb[f0 + 0], 0.f);
                r0.y = fmaxf(m[1] + s_bb[f0 + 1], 0.f);
                r0.z = fmaxf(m[2] + s_bb[f0 + 2], 0.f);
                r0.w = fmaxf(m[3] + s_bb[f0 + 3], 0.f);
                r1.x = fmaxf(m[4] + s_bb[f0 + 4], 0.f);
                r1.y = fmaxf(m[5] + s_bb[f0 + 5], 0.f);
                r1.z = fmaxf(m[6] + s_bb[f0 + 6], 0.f);
                r1.w = fmaxf(m[7] + s_bb[f0 + 7], 0.f);
                *reinterpret_cast<float4*>(&out[i * C + f0])     = r0;
                *reinterpret_cast<float4*>(&out[i * C + f0 + 4]) = r1;
            }
        }
        __syncthreads();
    }
}

// ---------------------------------------------------------------------------
extern "C" void kernel_launch(void* const* d_in, const int* in_sizes, int n_in,
                              void* d_out, int out_size) {
    const float* pos    = (const float*)d_in[0];
    const float* normal = (const float*)d_in[1];
    const float* W1a = (const float*)d_in[2];
    const float* b1a = (const float*)d_in[3];
    const float* g1  = (const float*)d_in[4];
    const float* be1 = (const float*)d_in[5];
    const float* W1b = (const float*)d_in[6];
    const float* b1b = (const float*)d_in[7];
    const float* W2a = (const float*)d_in[8];
    const float* b2a = (const float*)d_in[9];
    const float* g2  = (const float*)d_in[10];
    const float* be2 = (const float*)d_in[11];
    const float* W2b = (const float*)d_in[12];
    const float* b2b = (const float*)d_in[13];
    const float* W3a = (const float*)d_in[14];
    const float* b3a = (const float*)d_in[15];
    const float* g3  = (const float*)d_in[16];
    const float* be3 = (const float*)d_in[17];
    const float* W3b = (const float*)d_in[18];
    const float* b3b = (const float*)d_in[19];

    float* out = (float*)d_out;
    float* h1 = out;
    float* h2 = out + NPTS * 64;
    float* h3 = out + NPTS * 128;

    const int SMEM64  = (64 * 64  + 4 * 64 * 20  + 3 * 64  + 3 * 64)  * 4;
    const int SMEM128 = (128 * 128 + 4 * 128 * 20 + 3 * 128 + 3 * 128) * 4;
    cudaFuncSetAttribute((const void*)edge_kernel<64, 8, 8>,
                         cudaFuncAttributeMaxDynamicSharedMemorySize, SMEM64);
    cudaFuncSetAttribute((const void*)edge_kernel<128, 16, 8>,
                         cudaFuncAttributeMaxDynamicSharedMemorySize, SMEM128);

    pos4_kernel<<<NPTS / 256, 256>>>(pos);
    knn_kernel<<<NPTS / (WPB * RPW), 32 * WPB>>>();

    proj_kernel<6, 64, true><<<NPTS / 8, 128>>>(nullptr, pos, normal, W1a, b1a);
    edge_kernel<64, 8, 8><<<NPTS / 8, 128, SMEM64>>>(pos, W1a, 6, g1, be1, W1b, b1b, h1);

    proj_kernel<64, 64, false><<<NPTS / 8, 128>>>(h1, nullptr, nullptr, W2a, b2a);
    edge_kernel<64, 8, 8><<<NPTS / 8, 128, SMEM64>>>(pos, W2a, 64, g2, be2, W2b, b2b, h2);

    proj_kernel<64, 128, false><<<NPTS / 4, 128>>>(h2, nullptr, nullptr, W3a, b3a);
    edge_kernel<128, 16, 8><<<NPTS / 8, 256, SMEM128>>>(pos, W3a, 64, g3, be3, W3b, b3b, h3);
}

// round 6
// speedup vs baseline: 1.0421x; 1.0421x over previous
#include <cuda_runtime.h>

#define NPTS 16384
#define KNB  16

// Scratch (no allocations allowed).
__device__ __align__(16) float g_A[NPTS * 128];
__device__ int g_nbr[NPTS * KNB];
__device__ __align__(16) float4 g_pos4[NPTS];

// ---------------------------------------------------------------------------
// Packed f32x2 helpers (sm_103a FFMA2 path; ptxas never emits it from C++).
// ---------------------------------------------------------------------------
__device__ __forceinline__ unsigned long long fdup(float x) {
    unsigned long long r;
    asm("mov.b64 %0, {%1, %1};" : "=l"(r) : "f"(x));
    return r;
}
__device__ __forceinline__ void fma2(unsigned long long& d, unsigned long long a,
                                     unsigned long long b) {
    asm("fma.rn.f32x2 %0, %1, %2, %0;" : "+l"(d) : "l"(a), "l"(b));
}
__device__ __forceinline__ float2 u2f(unsigned long long v) {
    float2 r;
    asm("mov.b64 {%0, %1}, %2;" : "=f"(r.x), "=f"(r.y) : "l"(v));
    return r;
}

// ---------------------------------------------------------------------------
// Pack pos -> float4 (x,y,z,|p|^2) once.
// ---------------------------------------------------------------------------
__global__ void pos4_kernel(const float* __restrict__ pos) {
    const int i = blockIdx.x * blockDim.x + threadIdx.x;
    const float x = pos[3 * i], y = pos[3 * i + 1], z = pos[3 * i + 2];
    g_pos4[i] = make_float4(x, y, z, x * x + y * y + z * z);
}

// ---------------------------------------------------------------------------
// Warp-cooperative bitonic helpers on packed u64 keys.
// ---------------------------------------------------------------------------
__device__ __forceinline__ unsigned long long sort32(unsigned long long v, int lane) {
#pragma unroll
    for (int k = 2; k <= 32; k <<= 1) {
#pragma unroll
        for (int j = k >> 1; j > 0; j >>= 1) {
            const unsigned long long o = __shfl_xor_sync(0xffffffffu, v, j);
            const bool keepMin = (((lane & j) == 0) == ((lane & k) == 0));
            v = ((v < o) == keepMin) ? v : o;
        }
    }
    return v;
}

__device__ __forceinline__ unsigned long long merge_lower(unsigned long long a,
                                                          unsigned long long b,
                                                          int lane) {
    const unsigned long long br = __shfl_sync(0xffffffffu, b, 31 - lane);
    unsigned long long m = (a < br) ? a : br;
#pragma unroll
    for (int j = 16; j > 0; j >>= 1) {
        const unsigned long long o = __shfl_xor_sync(0xffffffffu, m, j);
        const bool keepMin = ((lane & j) == 0);
        m = ((m < o) == keepMin) ? m : o;
    }
    return m;
}

__device__ __forceinline__ void flush_merge(unsigned long long& v,
                                            unsigned long long& kth,
                                            const unsigned long long* buf,
                                            int cnt, int lane) {
    __syncwarp();
    unsigned long long b0 = (lane < cnt) ? buf[lane] : ~0ull;
    b0 = sort32(b0, lane);
    if (cnt > 32) {
        unsigned long long b1 = (32 + lane < cnt) ? buf[32 + lane] : ~0ull;
        b1 = sort32(b1, lane);
        b0 = merge_lower(b0, b1, lane);
    }
    v = merge_lower(v, b0, lane);
    kth = __shfl_sync(0xffffffffu, v, 15);
}

// ---------------------------------------------------------------------------
// KNN: R4-exact version (known-good 642us baseline).
// ---------------------------------------------------------------------------
#define WPB  16
#define TILE 1024

__global__ void __launch_bounds__(32 * WPB) knn_kernel() {
    __shared__ float4 s_cand[TILE];
    __shared__ unsigned long long s_buf[WPB][64];

    const int lane = threadIdx.x & 31;
    const int w    = threadIdx.x >> 5;
    const int row  = blockIdx.x * WPB + w;
    const float4 p = g_pos4[row];

    unsigned long long v   = ~0ull;
    unsigned long long kth = ~0ull;
    int bufcnt = 0;

    for (int base = 0; base < NPTS; base += TILE) {
        __syncthreads();
        for (int i = threadIdx.x; i < TILE; i += 32 * WPB) s_cand[i] = g_pos4[base + i];
        __syncthreads();
#pragma unroll 4
        for (int i = 0; i < TILE; i += 32) {
            const float4 c = s_cand[i + lane];
            const float dot = fmaf(p.x, c.x, fmaf(p.y, c.y, p.z * c.z));
            const float d2  = fmaf(-2.f, dot, p.w + c.w);
            unsigned u = __float_as_uint(d2);
            u = (u & 0x80000000u) ? ~u : (u | 0x80000000u);
            const unsigned long long key =
                ((unsigned long long)u << 32) | (unsigned)(base + i + lane);
            const bool pred = key < kth;
            const unsigned bal = __ballot_sync(0xffffffffu, pred);
            if (bal) {
                if (pred)
                    s_buf[w][bufcnt + __popc(bal & ((1u << lane) - 1u))] = key;
                bufcnt += __popc(bal);
                if (bufcnt > 32) {
                    flush_merge(v, kth, s_buf[w], bufcnt, lane);
                    bufcnt = 0;
                }
            }
        }
    }
    if (bufcnt) flush_merge(v, kth, s_buf[w], bufcnt, lane);
    if (lane < KNB) g_nbr[row * KNB + lane] = (int)(v & 0xFFFFFFFFull);
}

// ---------------------------------------------------------------------------
// Node projection (unchanged).
// ---------------------------------------------------------------------------
template <int CIN, int C, bool FIRST>
__global__ void __launch_bounds__(128) proj_kernel(const float* __restrict__ x,
                                                   const float* __restrict__ pos,
                                                   const float* __restrict__ nrm,
                                                   const float* __restrict__ Wa,
                                                   const float* __restrict__ ba) {
    constexpr int TPN = C / 4;
    __shared__ __align__(16) float sW[CIN * C];
    __shared__ __align__(16) float sb[C];
    const int t = threadIdx.x;
    for (int i = t; i < CIN * C; i += 128) sW[i] = Wa[i];
    for (int i = t; i < C; i += 128) sb[i] = ba[i];
    __syncthreads();

    const int n  = blockIdx.x * (128 / TPN) + t / TPN;
    const int c0 = (t % TPN) * 4;
    float4 acc = *reinterpret_cast<const float4*>(&sb[c0]);
#pragma unroll
    for (int k = 0; k < CIN; ++k) {
        float xv;
        if (FIRST) xv = (k < 3) ? pos[n * 3 + k] : nrm[n * 3 + (k - 3)];
        else       xv = x[n * CIN + k];
        const float4 w = *reinterpret_cast<const float4*>(&sW[k * C + c0]);
        acc.x = fmaf(xv, w.x, acc.x);
        acc.y = fmaf(xv, w.y, acc.y);
        acc.z = fmaf(xv, w.z, acc.z);
        acc.w = fmaf(xv, w.w, acc.w);
    }
    *reinterpret_cast<float4*>(&g_A[n * C + c0]) = acc;
}

// ---------------------------------------------------------------------------
// Fused edge kernel. R6: phase-3 mini-GEMM uses packed f32x2 FMA (FFMA2):
// 4 edges x 4 channel-pairs of u64 accumulators; weight pairs come directly
// from the LDS.128 (ulonglong2 view); h duplicated via mov.b64 {r,r}.
// Per-lane rn arithmetic identical to scalar fmaf -> bitwise same results.
// ---------------------------------------------------------------------------
template <int C, int G, int NPB>
__global__ void __launch_bounds__(2 * C) edge_kernel(
    const float* __restrict__ pos,
    const float* __restrict__ Wa, int cin_node,
    const float* __restrict__ gmm, const float* __restrict__ bta,
    const float* __restrict__ Wb,  const float* __restrict__ bb,
    float* __restrict__ out) {
    constexpr int B  = 2 * C;
    constexpr int HS = 20;
    constexpr int NG = 4;
    extern __shared__ float smem[];
    float* s_Wb   = smem;
    float* s_H    = s_Wb + C * C;
    float* s_Wrel = s_H + NG * C * HS;
    float* s_g    = s_Wrel + 3 * C;
    float* s_b    = s_g + C;
    float* s_bb   = s_b + C;

    const int t = threadIdx.x;
    for (int i = t; i < C * C; i += B) s_Wb[i] = Wb[i];
    for (int i = t; i < 3 * C; i += B) s_Wrel[i] = Wa[cin_node * C + i];
    for (int i = t; i < C; i += B) { s_g[i] = gmm[i]; s_b[i] = bta[i]; s_bb[i] = bb[i]; }
    __syncthreads();

    const int e    = t & 15;
    const int g    = t >> 4;
    const int lane = t & 31;
    const int w    = t >> 5;
    const int et   = lane & 3;
    const int fi   = lane >> 2;
    const int q3   = (C == 128) ? (w >> 1) : w;
    const int f0   = ((C == 128) ? (w & 1) * 64 : 0) + fi * 8;

    for (int s0 = 0; s0 < NPB; s0 += NG) {
        // ---- phase 1 + 2 : normalized H^T into smem ----
#pragma unroll
        for (int q = 0; q < NG; ++q) {
            const int i = blockIdx.x * NPB + s0 + q;
            float* Hq = s_H + q * C * HS;
            const int j = g_nbr[i * KNB + e];
            const float rx = pos[j * 3 + 0] - pos[i * 3 + 0];
            const float ry = pos[j * 3 + 1] - pos[i * 3 + 1];
            const float rz = pos[j * 3 + 2] - pos[i * 3 + 2];
            const int c0 = g * 8;
            const float* Ar = g_A + j * C + c0;
            const float4 a0 = *reinterpret_cast<const float4*>(Ar);
            const float4 a1 = *reinterpret_cast<const float4*>(Ar + 4);
            float h[8] = {a0.x, a0.y, a0.z, a0.w, a1.x, a1.y, a1.z, a1.w};
            float sum = 0.f;
#pragma unroll
            for (int cc = 0; cc < 8; ++cc) {
                const int c = c0 + cc;
                h[cc] = h[cc] + rx * s_Wrel[c] + ry * s_Wrel[C + c] + rz * s_Wrel[2 * C + c];
                sum += h[cc];
            }
            const float mean = sum * 0.125f;
            float vs = 0.f;
#pragma unroll
            for (int cc = 0; cc < 8; ++cc) { const float d = h[cc] - mean; vs = fmaf(d, d, vs); }
            const float inv = rsqrtf(fmaf(vs, 0.125f, 1e-5f));
#pragma unroll
            for (int cc = 0; cc < 8; ++cc) {
                const int c = c0 + cc;
                const float vv = fmaf((h[cc] - mean) * inv, s_g[c], s_b[c]);
                Hq[c * HS + e] = fmaxf(vv, 0.f);
            }
        }
        __syncthreads();
        // ---- phase 3 : warp-per-node mini-GEMM, FFMA2 4x(4x2) tile ----
        {
            const int i = blockIdx.x * NPB + s0 + q3;
            const float* Hq = s_H + q3 * C * HS;
            unsigned long long acc2[4][4];
#pragma unroll
            for (int a = 0; a < 4; ++a)
#pragma unroll
                for (int fp = 0; fp < 4; ++fp) acc2[a][fp] = 0ull;

#pragma unroll 4
            for (int c = 0; c < C; ++c) {
                const float4 h4 = *reinterpret_cast<const float4*>(&Hq[c * HS + et * 4]);
                const ulonglong2 wA = *reinterpret_cast<const ulonglong2*>(&s_Wb[c * C + f0]);
                const ulonglong2 wC = *reinterpret_cast<const ulonglong2*>(&s_Wb[c * C + f0 + 4]);
                const unsigned long long wv[4] = {wA.x, wA.y, wC.x, wC.y};
                const unsigned long long hh[4] = {fdup(h4.x), fdup(h4.y), fdup(h4.z), fdup(h4.w)};
#pragma unroll
                for (int a = 0; a < 4; ++a)
#pragma unroll
                    for (int fp = 0; fp < 4; ++fp)
                        fma2(acc2[a][fp], hh[a], wv[fp]);
            }
            float m[8];
#pragma unroll
            for (int fp = 0; fp < 4; ++fp) {
                const float2 v0 = u2f(acc2[0][fp]);
                const float2 v1 = u2f(acc2[1][fp]);
                const float2 v2 = u2f(acc2[2][fp]);
                const float2 v3 = u2f(acc2[3][fp]);
                m[2 * fp]     = fmaxf(fmaxf(v0.x, v1.x), fmaxf(v2.x, v3.x));
                m[2 * fp + 1] = fmaxf(fmaxf(v0.y, v1.y), fmaxf(v2.y, v3.y));
            }
#pragma unroll
            for (int f = 0; f < 8; ++f) {
                m[f] = fmaxf(m[f], __shfl_xor_sync(0xffffffffu, m[f], 1));
                m[f] = fmaxf(m[f], __shfl_xor_sync(0xffffffffu, m[f], 2));
            }
            if (et == 0) {
                float4 r0, r1;
                r0.x = fmaxf(m[0] + s_bb[f0 + 0], 0.f);
                r0.y = fmaxf(m[1] + s_bb[f0 + 1], 0.f);
                r0.z = fmaxf(m[2] + s_bb[f0 + 2], 0.f);
                r0.w = fmaxf(m[3] + s_bb[f0 + 3], 0.f);
                r1.x = fmaxf(m[4] + s_bb[f0 + 4], 0.f);
                r1.y = fmaxf(m[5] + s_bb[f0 + 5], 0.f);
                r1.z = fmaxf(m[6] + s_bb[f0 + 6], 0.f);
                r1.w = fmaxf(m[7] + s_bb[f0 + 7], 0.f);
                *reinterpret_cast<float4*>(&out[i * C + f0])     = r0;
                *reinterpret_cast<float4*>(&out[i * C + f0 + 4]) = r1;
            }
        }
        __syncthreads();
    }
}

// ---------------------------------------------------------------------------
extern "C" void kernel_launch(void* const* d_in, const int* in_sizes, int n_in,
                              void* d_out, int out_size) {
    const float* pos    = (const float*)d_in[0];
    const float* normal = (const float*)d_in[1];
    const float* W1a = (const float*)d_in[2];
    const float* b1a = (const float*)d_in[3];
    const float* g1  = (const float*)d_in[4];
    const float* be1 = (const float*)d_in[5];
    const float* W1b = (const float*)d_in[6];
    const float* b1b = (const float*)d_in[7];
    const float* W2a = (const float*)d_in[8];
    const float* b2a = (const float*)d_in[9];
    const float* g2  = (const float*)d_in[10];
    const float* be2 = (const float*)d_in[11];
    const float* W2b = (const float*)d_in[12];
    const float* b2b = (const float*)d_in[13];
    const float* W3a = (const float*)d_in[14];
    const float* b3a = (const float*)d_in[15];
    const float* g3  = (const float*)d_in[16];
    const float* be3 = (const float*)d_in[17];
    const float* W3b = (const float*)d_in[18];
    const float* b3b = (const float*)d_in[19];

    float* out = (float*)d_out;
    float* h1 = out;
    float* h2 = out + NPTS * 64;
    float* h3 = out + NPTS * 128;

    const int SMEM64  = (64 * 64  + 4 * 64 * 20  + 3 * 64  + 3 * 64)  * 4;
    const int SMEM128 = (128 * 128 + 4 * 128 * 20 + 3 * 128 + 3 * 128) * 4;
    cudaFuncSetAttribute((const void*)edge_kernel<64, 8, 8>,
                         cudaFuncAttributeMaxDynamicSharedMemorySize, SMEM64);
    cudaFuncSetAttribute((const void*)edge_kernel<128, 16, 8>,
                         cudaFuncAttributeMaxDynamicSharedMemorySize, SMEM128);

    pos4_kernel<<<NPTS / 256, 256>>>(pos);
    knn_kernel<<<NPTS / WPB, 32 * WPB>>>();

    proj_kernel<6, 64, true><<<NPTS / 8, 128>>>(nullptr, pos, normal, W1a, b1a);
    edge_kernel<64, 8, 8><<<NPTS / 8, 128, SMEM64>>>(pos, W1a, 6, g1, be1, W1b, b1b, h1);

    proj_kernel<64, 64, false><<<NPTS / 8, 128>>>(h1, nullptr, nullptr, W2a, b2a);
    edge_kernel<64, 8, 8><<<NPTS / 8, 128, SMEM64>>>(pos, W2a, 64, g2, be2, W2b, b2b, h2);

    proj_kernel<64, 128, false><<<NPTS / 4, 128>>>(h2, nullptr, nullptr, W3a, b3a);
    edge_kernel<128, 16, 8><<<NPTS / 8, 256, SMEM128>>>(pos, W3a, 64, g3, be3, W3b, b3b, h3);
}